// round 13
// baseline (speedup 1.0000x reference)
#include <cuda_runtime.h>
#include <cuda_fp16.h>
#include <cstdint>
#include <math.h>

#define N_BATCH 64
#define DIM     512
#define CQ      512
#define TT      1024
#define WW      128
#define SCALE   0.04419417382415922f  // 512^-0.5

#define NSLOT   16

// Scratch (device globals)
static __device__ __half   g_wh[(size_t)N_BATCH * CQ * TT];         // 64 MB unnormalized exp (half)
static __device__ uint32_t g_qh[(size_t)N_BATCH * (DIM/2) * CQ];    // 32 MB Q pair-interleaved half2 (scaled)
static __device__ uint32_t g_kh[(size_t)N_BATCH * (DIM/2) * TT];    // 64 MB K pair-interleaved half2
static __device__ uint32_t g_vh[(size_t)N_BATCH * DIM * (TT/2)];    // 64 MB V half (t-pairs)
static __device__ float    g_Spart[NSLOT * N_BATCH * CQ];           // partial row sums
static __device__ float    g_Sinv[N_BATCH * CQ];                    // reciprocal sums

// ---------------------------------------------------------------------------
__device__ __forceinline__ uint32_t smem_u32(const void* p) {
    uint32_t a;
    asm("{ .reg .u64 t; cvta.to.shared.u64 t, %1; cvt.u32.u64 %0, t; }"
        : "=r"(a) : "l"(p));
    return a;
}

__device__ __forceinline__ uint32_t f22h(float x, float y) {
    __half2 h = __floats2half2_rn(x, y);
    return *(uint32_t*)&h;
}

__device__ __forceinline__ void mma_f16(float c[4],
                                        uint32_t a0, uint32_t a1, uint32_t a2, uint32_t a3,
                                        uint32_t b0, uint32_t b1) {
    asm volatile(
        "mma.sync.aligned.m16n8k16.row.col.f32.f16.f16.f32 "
        "{%0,%1,%2,%3}, {%4,%5,%6,%7}, {%8,%9}, {%0,%1,%2,%3};"
        : "+f"(c[0]), "+f"(c[1]), "+f"(c[2]), "+f"(c[3])
        : "r"(a0), "r"(a1), "r"(a2), "r"(a3), "r"(b0), "r"(b1));
}

__device__ __forceinline__ void cp16(uint32_t saddr, const void* gaddr) {
    asm volatile("cp.async.cg.shared.global [%0], [%1], 16;"
        :: "r"(saddr), "l"(gaddr) : "memory");
}

__device__ __forceinline__ void g_mmas8(float acc[4][8][4],
                                        uint32_t a[4][4], uint32_t b[8][2])
{
    #pragma unroll
    for (int i = 0; i < 4; i++)
        #pragma unroll
        for (int j = 0; j < 8; j++)
            mma_f16(acc[i][j], a[i][0], a[i][1], a[i][2], a[i][3],
                    b[j][0], b[j][1]);
}

// ---------------------------------------------------------------------------
// Conversion passes
// ---------------------------------------------------------------------------
__global__ __launch_bounds__(128) void pairify(
    const float* __restrict__ in, uint32_t* __restrict__ out,
    int W, float mul)
{
    const int n   = blockIdx.z;
    const int p   = blockIdx.y;
    const int P   = gridDim.y;
    const int col = (blockIdx.x * 128 + threadIdx.x) * 4;

    const float* r0 = in + ((size_t)n * 2 * P + 2 * p) * W + col;
    const float* r1 = r0 + W;
    float4 a = *(const float4*)r0;
    float4 b = *(const float4*)r1;
    uint4 o;
    o.x = f22h(a.x * mul, b.x * mul);
    o.y = f22h(a.y * mul, b.y * mul);
    o.z = f22h(a.z * mul, b.z * mul);
    o.w = f22h(a.w * mul, b.w * mul);
    *(uint4*)(out + ((size_t)n * P + p) * W + col) = o;
}

__global__ __launch_bounds__(256) void vconv(
    const float4* __restrict__ in, uint4* __restrict__ out)
{
    const size_t i = (size_t)blockIdx.x * 256 + threadIdx.x;
    float4 a = in[2 * i];
    float4 b = in[2 * i + 1];
    uint4 o;
    o.x = f22h(a.x, a.y);
    o.y = f22h(a.z, a.w);
    o.z = f22h(b.x, b.y);
    o.w = f22h(b.z, b.w);
    out[i] = o;
}

// ---------------------------------------------------------------------------
// GEMM1 (TN) + masked exp epilogue:
//   e[n][c][t] = mask ? exp((Q*SCALE)^T K) : 0 ; partial row sums to Spart.
// CTA 128(c) x 128(t), **128 threads**, 4 warps 2(m)x2(n) of 64x64,
// KC=32 (16 pairs), 4-stage cp.async, fragment double-buffer, 2 CTAs/SM.
// smem [kpair][x] pitch 136 words (mod 32 == 8 -> conflict-free).
// Stage: A [16][136]w + B [16][136]w = 17408 B.
// ---------------------------------------------------------------------------
#define S1      17408
#define SMEM1   (4 * S1)              // 69632

__device__ __forceinline__ void g1_frags(
    const uint32_t* __restrict__ As, const uint32_t* __restrict__ Bs,
    int kk, int mOff, int nOff, int g, int tig,
    uint32_t a[4][4], uint32_t b[8][2])
{
    #pragma unroll
    for (int i = 0; i < 4; i++) {
        const int mb = mOff + 16 * i;
        a[i][0] = As[(kk + tig    ) * 136 + mb + g    ];
        a[i][1] = As[(kk + tig    ) * 136 + mb + g + 8];
        a[i][2] = As[(kk + tig + 4) * 136 + mb + g    ];
        a[i][3] = As[(kk + tig + 4) * 136 + mb + g + 8];
    }
    #pragma unroll
    for (int j = 0; j < 8; j++) {
        const int nb = nOff + 8 * j + g;
        b[j][0] = Bs[(kk + tig    ) * 136 + nb];
        b[j][1] = Bs[(kk + tig + 4) * 136 + nb];
    }
}

__global__ __launch_bounds__(128, 2) void gemm_qk(
    const uint32_t* __restrict__ Qh, const uint32_t* __restrict__ Kh,
    __half* __restrict__ Wh, float* __restrict__ Spart,
    const float* __restrict__ ratios)
{
    extern __shared__ char sm[];
    const uint32_t sb = smem_u32(sm);

    const int tid  = threadIdx.x;
    const int wid  = tid >> 5;
    const int lane = tid & 31;
    const int g    = lane >> 2;
    const int tig  = lane & 3;
    const int mOff = (wid >> 1) * 64;   // 0,64  (c)
    const int nOff = (wid & 1) * 64;    // 0,64  (t)

    const int n  = blockIdx.z;
    const uint32_t* Qn = Qh + (size_t)n * (DIM/2) * CQ;
    const uint32_t* Kn = Kh + (size_t)n * (DIM/2) * TT;
    const int c0 = blockIdx.y * 128;
    const int t0 = blockIdx.x * 128;

    // loaders: pr = tid/8 (0..15 pair rows), lc = tid%8, 16 words each operand
    const int pr = tid >> 3;
    const int lc = tid & 7;
    const uint32_t* qsrc = Qn + (size_t)pr * CQ + c0 + lc * 16;
    const uint32_t* ksrc = Kn + (size_t)pr * TT + t0 + lc * 16;
    const uint32_t adst = sb + (uint32_t)(pr * 544 + lc * 64);
    const uint32_t bdst = sb + 8704u + (uint32_t)(pr * 544 + lc * 64);

    float acc[4][8][4];
    #pragma unroll
    for (int i = 0; i < 4; i++)
        #pragma unroll
        for (int j = 0; j < 8; j++)
            #pragma unroll
            for (int r = 0; r < 4; r++) acc[i][j][r] = 0.f;

    #pragma unroll
    for (int s = 0; s < 3; s++) {
        #pragma unroll
        for (int q = 0; q < 4; q++) {
            cp16(adst + s * S1 + q * 16, qsrc + (size_t)s * 16 * CQ + q * 4);
            cp16(bdst + s * S1 + q * 16, ksrc + (size_t)s * 16 * TT + q * 4);
        }
        asm volatile("cp.async.commit_group;" ::: "memory");
    }

    asm volatile("cp.async.wait_group 2;" ::: "memory");
    __syncthreads();

    uint32_t af[2][4][4], bf[2][8][2];
    g1_frags((const uint32_t*)(sm), (const uint32_t*)(sm + 8704),
             0, mOff, nOff, g, tig, af[0], bf[0]);

    for (int c = 0; c < 16; c++) {
        const uint32_t* As = (const uint32_t*)(sm + (c & 3) * S1);
        const uint32_t* Bs = (const uint32_t*)(sm + (c & 3) * S1 + 8704);

        // prefetch ks=1 frags, run ks=0 MMAs behind them
        g1_frags(As, Bs, 8, mOff, nOff, g, tig, af[1], bf[1]);
        g_mmas8(acc, af[0], bf[0]);

        // issue stage c+3
        {
            const int s = c + 3;
            if (s < 16) {
                #pragma unroll
                for (int q = 0; q < 4; q++) {
                    cp16(adst + (s & 3) * S1 + q * 16, qsrc + (size_t)s * 16 * CQ + q * 4);
                    cp16(bdst + (s & 3) * S1 + q * 16, ksrc + (size_t)s * 16 * TT + q * 4);
                }
            }
            asm volatile("cp.async.commit_group;" ::: "memory");
        }
        asm volatile("cp.async.wait_group 2;" ::: "memory");
        __syncthreads();

        // prefetch next chunk ks=0, run ks=1 MMAs
        if (c + 1 < 16) {
            const uint32_t* An = (const uint32_t*)(sm + ((c + 1) & 3) * S1);
            const uint32_t* Bn = (const uint32_t*)(sm + ((c + 1) & 3) * S1 + 8704);
            g1_frags(An, Bn, 0, mOff, nOff, g, tig, af[0], bf[0]);
        }
        g_mmas8(acc, af[1], bf[1]);
    }

    // ---- epilogue: mask + exp + half store + deterministic partial sums ----
    const float ratio = ratios[n];
    int vw = (int)floorf((float)WW * ratio + 0.5f);
    vw = vw > WW ? WW : vw;

    uint32_t* Ww = (uint32_t*)(Wh + (size_t)n * CQ * TT);
    float rsum[4][2];
    #pragma unroll
    for (int i = 0; i < 4; i++) { rsum[i][0] = 0.f; rsum[i][1] = 0.f; }

    #pragma unroll
    for (int i = 0; i < 4; i++) {
        const int row0 = c0 + mOff + 16 * i + g;
        #pragma unroll
        for (int j = 0; j < 8; j++) {
            const int wc   = nOff + 8 * j + 2 * tig;   // t % 128
            const int colb = t0 + wc;
            float e0 = (wc     < vw) ? __expf(acc[i][j][0]) : 0.f;
            float e1 = (wc + 1 < vw) ? __expf(acc[i][j][1]) : 0.f;
            float e2 = (wc     < vw) ? __expf(acc[i][j][2]) : 0.f;
            float e3 = (wc + 1 < vw) ? __expf(acc[i][j][3]) : 0.f;
            Ww[((size_t)row0 * TT + colb) >> 1]       = f22h(e0, e1);
            Ww[((size_t)(row0 + 8) * TT + colb) >> 1] = f22h(e2, e3);
            rsum[i][0] += e0 + e1;
            rsum[i][1] += e2 + e3;
        }
    }
    #pragma unroll
    for (int i = 0; i < 4; i++) {
        #pragma unroll
        for (int h = 0; h < 2; h++) {
            float v = rsum[i][h];
            v += __shfl_xor_sync(0xffffffffu, v, 1);
            v += __shfl_xor_sync(0xffffffffu, v, 2);
            rsum[i][h] = v;
        }
    }
    if (tig == 0) {
        const int slot = blockIdx.x * 2 + (wid & 1);   // 8 t-blocks x 2 warp n-cols
        float* sp = Spart + (size_t)slot * N_BATCH * CQ + (size_t)n * CQ;
        #pragma unroll
        for (int i = 0; i < 4; i++) {
            sp[c0 + mOff + 16 * i + g    ] = rsum[i][0];
            sp[c0 + mOff + 16 * i + g + 8] = rsum[i][1];
        }
    }
}

// ---------------------------------------------------------------------------
__global__ __launch_bounds__(256) void sinv_kernel(
    const float* __restrict__ Spart, float* __restrict__ Sinv)
{
    const int idx = blockIdx.x * 256 + threadIdx.x;
    float s = 0.f;
    #pragma unroll
    for (int k = 0; k < NSLOT; k++)
        s += Spart[(size_t)k * N_BATCH * CQ + idx];
    Sinv[idx] = 1.0f / s;
}

// ---------------------------------------------------------------------------
// GEMM2 (NT): O[n][d][c] = Sinv[c] * sum_t V[d][t] * e[c][t]
// CTA 128(d) x 128(c), **128 threads**, 4 warps 2(m)x2(n) of 64x64,
// KC=32, 4-stage cp.async, fragment double-buffer, 2 CTAs/SM.
// smem [x][kpair] pitch 20 words. Stage: A[128][20]w + B[128][20]w = 20480 B.
// ---------------------------------------------------------------------------
#define S2      20480
#define SMEM2   (4 * S2)              // 81920

__device__ __forceinline__ void g2_frags(
    const uint32_t* __restrict__ As, const uint32_t* __restrict__ Bs,
    int kk, int mOff, int nOff, int g, int tig,
    uint32_t a[4][4], uint32_t b[8][2])
{
    #pragma unroll
    for (int i = 0; i < 4; i++) {
        const int mb = mOff + 16 * i;
        a[i][0] = As[(mb + g    ) * 20 + kk + tig    ];
        a[i][1] = As[(mb + g + 8) * 20 + kk + tig    ];
        a[i][2] = As[(mb + g    ) * 20 + kk + tig + 4];
        a[i][3] = As[(mb + g + 8) * 20 + kk + tig + 4];
    }
    #pragma unroll
    for (int j = 0; j < 8; j++) {
        const int nb = nOff + 8 * j + g;
        b[j][0] = Bs[nb * 20 + kk + tig    ];
        b[j][1] = Bs[nb * 20 + kk + tig + 4];
    }
}

__global__ __launch_bounds__(128, 2) void gemm_wv(
    const uint32_t* __restrict__ Vh, const uint32_t* __restrict__ Wp,
    const float* __restrict__ Sinv, float* __restrict__ O)
{
    extern __shared__ char sm[];
    const uint32_t sb = smem_u32(sm);

    const int tid  = threadIdx.x;
    const int wid  = tid >> 5;
    const int lane = tid & 31;
    const int g    = lane >> 2;
    const int tig  = lane & 3;
    const int mOff = (wid >> 1) * 64;   // 0,64 (d)
    const int nOff = (wid & 1) * 64;    // 0,64 (c)

    const int n  = blockIdx.z;
    const uint32_t* Vn = Vh + (size_t)n * DIM * (TT/2);
    const uint32_t* Wn = Wp + (size_t)n * CQ  * (TT/2);
    float*          Ob = O  + (size_t)n * DIM * CQ;
    const int d0 = blockIdx.y * 128;
    const int c0 = blockIdx.x * 128;

    // loaders: each thread owns one A row (d0+tid) and one B row (c0+tid);
    // 16 words (4 cp16) per row per stage.
    const uint32_t* vsrc = Vn + (size_t)(d0 + tid) * (TT/2);
    const uint32_t* wsrc = Wn + (size_t)(c0 + tid) * (TT/2);
    const uint32_t adst = sb + (uint32_t)(tid * 80);
    const uint32_t bdst = sb + 10240u + (uint32_t)(tid * 80);

    float acc[4][8][4];
    #pragma unroll
    for (int i = 0; i < 4; i++)
        #pragma unroll
        for (int j = 0; j < 8; j++)
            #pragma unroll
            for (int r = 0; r < 4; r++) acc[i][j][r] = 0.f;

    #pragma unroll
    for (int s = 0; s < 3; s++) {
        #pragma unroll
        for (int q = 0; q < 4; q++) {
            cp16(adst + s * S2 + q * 16, vsrc + s * 16 + q * 4);
            cp16(bdst + s * S2 + q * 16, wsrc + s * 16 + q * 4);
        }
        asm volatile("cp.async.commit_group;" ::: "memory");
    }

    asm volatile("cp.async.wait_group 2;" ::: "memory");
    __syncthreads();

    uint32_t af[2][4][4], bf[2][8][2];
    g2_frags((const uint32_t*)(sm), (const uint32_t*)(sm + 10240),
             0, mOff, nOff, g, tig, af[0], bf[0]);

    for (int c = 0; c < 32; c++) {
        const uint32_t* As = (const uint32_t*)(sm + (c & 3) * S2);
        const uint32_t* Bs = (const uint32_t*)(sm + (c & 3) * S2 + 10240);

        g2_frags(As, Bs, 8, mOff, nOff, g, tig, af[1], bf[1]);
        g_mmas8(acc, af[0], bf[0]);

        {
            const int s = c + 3;
            if (s < 32) {
                #pragma unroll
                for (int q = 0; q < 4; q++) {
                    cp16(adst + (s & 3) * S2 + q * 16, vsrc + (size_t)s * 16 + q * 4);
                    cp16(bdst + (s & 3) * S2 + q * 16, wsrc + (size_t)s * 16 + q * 4);
                }
            }
            asm volatile("cp.async.commit_group;" ::: "memory");
        }
        asm volatile("cp.async.wait_group 2;" ::: "memory");
        __syncthreads();

        if (c + 1 < 32) {
            const uint32_t* An = (const uint32_t*)(sm + ((c + 1) & 3) * S2);
            const uint32_t* Bn = (const uint32_t*)(sm + ((c + 1) & 3) * S2 + 10240);
            g2_frags(An, Bn, 0, mOff, nOff, g, tig, af[0], bf[0]);
        }
        g_mmas8(acc, af[1], bf[1]);
    }

    const float* Sn = Sinv + (size_t)n * CQ;
    #pragma unroll
    for (int i = 0; i < 4; i++) {
        const int row0 = d0 + mOff + 16 * i + g;
        #pragma unroll
        for (int j = 0; j < 8; j++) {
            const int colb = c0 + nOff + 8 * j + 2 * tig;
            const float si0 = Sn[colb];
            const float si1 = Sn[colb + 1];
            *(float2*)(Ob + (size_t)row0 * CQ + colb) =
                make_float2(acc[i][j][0] * si0, acc[i][j][1] * si1);
            *(float2*)(Ob + (size_t)(row0 + 8) * CQ + colb) =
                make_float2(acc[i][j][2] * si0, acc[i][j][3] * si1);
        }
    }
}

// ---------------------------------------------------------------------------
extern "C" void kernel_launch(void* const* d_in, const int* in_sizes, int n_in,
                              void* d_out, int out_size)
{
    const float* query  = (const float*)d_in[0];  // [64, 512, 512]
    const float* key    = (const float*)d_in[1];  // [64, 512, 1024]
    const float* value  = (const float*)d_in[2];  // [64, 512, 1024]
    const float* ratios = (const float*)d_in[3];  // [64]
    float* out = (float*)d_out;                   // [64, 512, 512]

    __half*   wh = nullptr;
    uint32_t *qh = nullptr, *kh = nullptr, *vh = nullptr;
    float    *sp = nullptr, *si = nullptr;
    cudaGetSymbolAddress((void**)&wh, g_wh);
    cudaGetSymbolAddress((void**)&qh, g_qh);
    cudaGetSymbolAddress((void**)&kh, g_kh);
    cudaGetSymbolAddress((void**)&vh, g_vh);
    cudaGetSymbolAddress((void**)&sp, g_Spart);
    cudaGetSymbolAddress((void**)&si, g_Sinv);

    cudaFuncSetAttribute(gemm_qk, cudaFuncAttributeMaxDynamicSharedMemorySize, SMEM1);
    cudaFuncSetAttribute(gemm_wv, cudaFuncAttributeMaxDynamicSharedMemorySize, SMEM2);

    // 0) conversions
    pairify<<<dim3(CQ / 512, DIM / 2, N_BATCH), 128>>>(query, qh, CQ, SCALE);
    pairify<<<dim3(TT / 512, DIM / 2, N_BATCH), 128>>>(key,   kh, TT, 1.0f);
    {
        const size_t n8 = (size_t)N_BATCH * DIM * TT / 8;
        vconv<<<(unsigned)(n8 / 256), 256>>>((const float4*)value, (uint4*)vh);
    }
    // 1) e = mask?exp((Q*SCALE)^T K):0  + partial sums
    {
        dim3 grid(TT / 128, CQ / 128, N_BATCH);  // (8, 4, 64)
        gemm_qk<<<grid, 128, SMEM1>>>(qh, kh, wh, sp, ratios);
    }
    // 2) Sinv = 1/rowsum
    sinv_kernel<<<(N_BATCH * CQ) / 256, 256>>>(sp, si);
    // 3) out = Sinv .* (V x e^T)
    {
        dim3 grid(CQ / 128, DIM / 128, N_BATCH);  // (4, 4, 64)
        gemm_wv<<<grid, 128, SMEM2>>>(vh, (const uint32_t*)wh, si, out);
    }
}

// round 14
// speedup vs baseline: 1.1176x; 1.1176x over previous
#include <cuda_runtime.h>
#include <cuda_fp16.h>
#include <cstdint>
#include <math.h>

#define N_BATCH 64
#define DIM     512
#define CQ      512
#define TT      1024
#define WW      128
#define SCALE   0.04419417382415922f  // 512^-0.5

#define NSLOT   16

// Scratch (device globals)
static __device__ __half   g_wh[(size_t)N_BATCH * CQ * TT];         // 64 MB unnormalized exp (half)
static __device__ uint32_t g_qh[(size_t)N_BATCH * (DIM/2) * CQ];    // 32 MB Q pair-interleaved half2 (scaled)
static __device__ uint32_t g_kh[(size_t)N_BATCH * (DIM/2) * TT];    // 64 MB K pair-interleaved half2
static __device__ uint32_t g_vh[(size_t)N_BATCH * DIM * (TT/2)];    // 64 MB V half (t-pairs)
static __device__ float    g_Spart[NSLOT * N_BATCH * CQ];           // partial row sums
static __device__ float    g_Sinv[N_BATCH * CQ];                    // reciprocal sums

// ---------------------------------------------------------------------------
__device__ __forceinline__ uint32_t smem_u32(const void* p) {
    uint32_t a;
    asm("{ .reg .u64 t; cvta.to.shared.u64 t, %1; cvt.u32.u64 %0, t; }"
        : "=r"(a) : "l"(p));
    return a;
}

__device__ __forceinline__ uint32_t f22h(float x, float y) {
    __half2 h = __floats2half2_rn(x, y);
    return *(uint32_t*)&h;
}

__device__ __forceinline__ void mma_f16(float c[4],
                                        uint32_t a0, uint32_t a1, uint32_t a2, uint32_t a3,
                                        uint32_t b0, uint32_t b1) {
    asm volatile(
        "mma.sync.aligned.m16n8k16.row.col.f32.f16.f16.f32 "
        "{%0,%1,%2,%3}, {%4,%5,%6,%7}, {%8,%9}, {%0,%1,%2,%3};"
        : "+f"(c[0]), "+f"(c[1]), "+f"(c[2]), "+f"(c[3])
        : "r"(a0), "r"(a1), "r"(a2), "r"(a3), "r"(b0), "r"(b1));
}

__device__ __forceinline__ void cp16(uint32_t saddr, const void* gaddr) {
    asm volatile("cp.async.cg.shared.global [%0], [%1], 16;"
        :: "r"(saddr), "l"(gaddr) : "memory");
}

__device__ __forceinline__ void ldsm4(uint32_t r[4], uint32_t addr) {
    asm volatile("ldmatrix.sync.aligned.m8n8.x4.shared.b16 {%0,%1,%2,%3}, [%4];"
        : "=r"(r[0]), "=r"(r[1]), "=r"(r[2]), "=r"(r[3]) : "r"(addr));
}

// ---------------------------------------------------------------------------
// Conversion passes
// ---------------------------------------------------------------------------
__global__ __launch_bounds__(128) void pairify(
    const float* __restrict__ in, uint32_t* __restrict__ out,
    int W, float mul)
{
    const int n   = blockIdx.z;
    const int p   = blockIdx.y;
    const int P   = gridDim.y;
    const int col = (blockIdx.x * 128 + threadIdx.x) * 4;

    const float* r0 = in + ((size_t)n * 2 * P + 2 * p) * W + col;
    const float* r1 = r0 + W;
    float4 a = *(const float4*)r0;
    float4 b = *(const float4*)r1;
    uint4 o;
    o.x = f22h(a.x * mul, b.x * mul);
    o.y = f22h(a.y * mul, b.y * mul);
    o.z = f22h(a.z * mul, b.z * mul);
    o.w = f22h(a.w * mul, b.w * mul);
    *(uint4*)(out + ((size_t)n * P + p) * W + col) = o;
}

__global__ __launch_bounds__(256) void vconv(
    const float4* __restrict__ in, uint4* __restrict__ out)
{
    const size_t i = (size_t)blockIdx.x * 256 + threadIdx.x;
    float4 a = in[2 * i];
    float4 b = in[2 * i + 1];
    uint4 o;
    o.x = f22h(a.x, a.y);
    o.y = f22h(a.z, a.w);
    o.z = f22h(b.x, b.y);
    o.w = f22h(b.z, b.w);
    out[i] = o;
}

// ---------------------------------------------------------------------------
// GEMM1 (TN) + masked exp epilogue (EXACT R10 config — best known):
//   e[n][c][t] = mask ? exp((Q*SCALE)^T K) : 0 ; partial row sums to Spart.
// CTA 256(c) x 128(t), 256 thr, warps 4(m)x2(n) of 64x64, KC=32,
// 4-stage cp.async, fragment register double-buffering.
// ---------------------------------------------------------------------------
#define S1      25600                 // 16896 + 8704
#define SMEM1   (4 * S1)

__device__ __forceinline__ void g1_frags(
    const uint32_t* __restrict__ As, const uint32_t* __restrict__ Bs,
    int kk, int mOff, int nOff, int g, int tig,
    uint32_t a[4][4], uint32_t b[8][2])
{
    #pragma unroll
    for (int i = 0; i < 4; i++) {
        const int mb = mOff + 16 * i;
        a[i][0] = As[(kk + tig    ) * 264 + mb + g    ];
        a[i][1] = As[(kk + tig    ) * 264 + mb + g + 8];
        a[i][2] = As[(kk + tig + 4) * 264 + mb + g    ];
        a[i][3] = As[(kk + tig + 4) * 264 + mb + g + 8];
    }
    #pragma unroll
    for (int j = 0; j < 8; j++) {
        const int nb = nOff + 8 * j + g;
        b[j][0] = Bs[(kk + tig    ) * 136 + nb];
        b[j][1] = Bs[(kk + tig + 4) * 136 + nb];
    }
}

__device__ __forceinline__ void g_mmas8(float acc[4][8][4],
                                        uint32_t a[4][4], uint32_t b[8][2])
{
    #pragma unroll
    for (int i = 0; i < 4; i++)
        #pragma unroll
        for (int j = 0; j < 8; j++)
            mma_f16(acc[i][j], a[i][0], a[i][1], a[i][2], a[i][3],
                    b[j][0], b[j][1]);
}

__global__ __launch_bounds__(256, 1) void gemm_qk(
    const uint32_t* __restrict__ Qh, const uint32_t* __restrict__ Kh,
    __half* __restrict__ Wh, float* __restrict__ Spart,
    const float* __restrict__ ratios)
{
    extern __shared__ char sm[];
    const uint32_t sb = smem_u32(sm);

    const int tid  = threadIdx.x;
    const int wid  = tid >> 5;
    const int lane = tid & 31;
    const int g    = lane >> 2;
    const int tig  = lane & 3;
    const int mOff = (wid >> 1) * 64;
    const int nOff = (wid & 1) * 64;

    const int n  = blockIdx.z;
    const uint32_t* Qn = Qh + (size_t)n * (DIM/2) * CQ;
    const uint32_t* Kn = Kh + (size_t)n * (DIM/2) * TT;
    const int c0 = blockIdx.y * 256;
    const int t0 = blockIdx.x * 128;

    const int pr = tid >> 4;
    const int lc = tid & 15;
    const uint32_t* qsrc = Qn + (size_t)pr * CQ + c0 + lc * 16;
    const uint32_t* ksrc = Kn + (size_t)pr * TT + t0 + lc * 8;
    const uint32_t adst = sb + (uint32_t)(pr * 1056 + lc * 64);
    const uint32_t bdst = sb + 16896u + (uint32_t)(pr * 544 + lc * 32);

    float acc[4][8][4];
    #pragma unroll
    for (int i = 0; i < 4; i++)
        #pragma unroll
        for (int j = 0; j < 8; j++)
            #pragma unroll
            for (int r = 0; r < 4; r++) acc[i][j][r] = 0.f;

    #pragma unroll
    for (int s = 0; s < 3; s++) {
        #pragma unroll
        for (int q = 0; q < 4; q++)
            cp16(adst + s * S1 + q * 16, qsrc + (size_t)s * 16 * CQ + q * 4);
        #pragma unroll
        for (int q = 0; q < 2; q++)
            cp16(bdst + s * S1 + q * 16, ksrc + (size_t)s * 16 * TT + q * 4);
        asm volatile("cp.async.commit_group;" ::: "memory");
    }

    asm volatile("cp.async.wait_group 2;" ::: "memory");
    __syncthreads();

    uint32_t af[2][4][4], bf[2][8][2];
    g1_frags((const uint32_t*)(sm), (const uint32_t*)(sm + 16896),
             0, mOff, nOff, g, tig, af[0], bf[0]);

    for (int c = 0; c < 16; c++) {
        const uint32_t* As = (const uint32_t*)(sm + (c & 3) * S1);
        const uint32_t* Bs = (const uint32_t*)(sm + (c & 3) * S1 + 16896);

        g1_frags(As, Bs, 8, mOff, nOff, g, tig, af[1], bf[1]);
        g_mmas8(acc, af[0], bf[0]);

        {
            const int s = c + 3;
            if (s < 16) {
                #pragma unroll
                for (int q = 0; q < 4; q++)
                    cp16(adst + (s & 3) * S1 + q * 16, qsrc + (size_t)s * 16 * CQ + q * 4);
                #pragma unroll
                for (int q = 0; q < 2; q++)
                    cp16(bdst + (s & 3) * S1 + q * 16, ksrc + (size_t)s * 16 * TT + q * 4);
            }
            asm volatile("cp.async.commit_group;" ::: "memory");
        }
        asm volatile("cp.async.wait_group 2;" ::: "memory");
        __syncthreads();

        if (c + 1 < 16) {
            const uint32_t* An = (const uint32_t*)(sm + ((c + 1) & 3) * S1);
            const uint32_t* Bn = (const uint32_t*)(sm + ((c + 1) & 3) * S1 + 16896);
            g1_frags(An, Bn, 0, mOff, nOff, g, tig, af[0], bf[0]);
        }
        g_mmas8(acc, af[1], bf[1]);
    }

    // ---- epilogue: mask + exp + half store + deterministic partial sums ----
    const float ratio = ratios[n];
    int vw = (int)floorf((float)WW * ratio + 0.5f);
    vw = vw > WW ? WW : vw;

    uint32_t* Ww = (uint32_t*)(Wh + (size_t)n * CQ * TT);
    float rsum[4][2];
    #pragma unroll
    for (int i = 0; i < 4; i++) { rsum[i][0] = 0.f; rsum[i][1] = 0.f; }

    #pragma unroll
    for (int i = 0; i < 4; i++) {
        const int row0 = c0 + mOff + 16 * i + g;
        #pragma unroll
        for (int j = 0; j < 8; j++) {
            const int wc   = nOff + 8 * j + 2 * tig;
            const int colb = t0 + wc;
            float e0 = (wc     < vw) ? __expf(acc[i][j][0]) : 0.f;
            float e1 = (wc + 1 < vw) ? __expf(acc[i][j][1]) : 0.f;
            float e2 = (wc     < vw) ? __expf(acc[i][j][2]) : 0.f;
            float e3 = (wc + 1 < vw) ? __expf(acc[i][j][3]) : 0.f;
            Ww[((size_t)row0 * TT + colb) >> 1]       = f22h(e0, e1);
            Ww[((size_t)(row0 + 8) * TT + colb) >> 1] = f22h(e2, e3);
            rsum[i][0] += e0 + e1;
            rsum[i][1] += e2 + e3;
        }
    }
    #pragma unroll
    for (int i = 0; i < 4; i++) {
        #pragma unroll
        for (int h = 0; h < 2; h++) {
            float v = rsum[i][h];
            v += __shfl_xor_sync(0xffffffffu, v, 1);
            v += __shfl_xor_sync(0xffffffffu, v, 2);
            rsum[i][h] = v;
        }
    }
    if (tig == 0) {
        const int slot = blockIdx.x * 2 + (wid & 1);
        float* sp = Spart + (size_t)slot * N_BATCH * CQ + (size_t)n * CQ;
        #pragma unroll
        for (int i = 0; i < 4; i++) {
            sp[c0 + mOff + 16 * i + g    ] = rsum[i][0];
            sp[c0 + mOff + 16 * i + g + 8] = rsum[i][1];
        }
    }
}

// ---------------------------------------------------------------------------
__global__ __launch_bounds__(256) void sinv_kernel(
    const float* __restrict__ Spart, float* __restrict__ Sinv)
{
    const int idx = blockIdx.x * 256 + threadIdx.x;
    float s = 0.f;
    #pragma unroll
    for (int k = 0; k < NSLOT; k++)
        s += Spart[(size_t)k * N_BATCH * CQ + idx];
    Sinv[idx] = 1.0f / s;
}

// ---------------------------------------------------------------------------
// GEMM2 (NT): O[n][d][c] = Sinv[c] * sum_t V[d][t] * e[c][t]
// R10 structure (CTA 128x128, 256 thr, warps 2(m)x4(n) of 64x32, KC=32,
// 4-stage cp.async, frag double-buffer) with scalar frag LDS replaced by
// ldmatrix.m8n8.x4 (non-trans). Pitch 20 words: 16B-group = 5*row + kg,
// 5 odd -> all 8 rows of each LDSM phase in distinct groups (conflict-free).
// Per warp-k16: 4 LDSM.x4 (A) + 2 LDSM.x4 (B) vs 24 scalar LDS before.
// ---------------------------------------------------------------------------
#define S2      20480                 // 10240 + 10240
#define SMEM2   (4 * S2)

__global__ __launch_bounds__(256, 1) void gemm_wv(
    const uint32_t* __restrict__ Vh, const uint32_t* __restrict__ Wp,
    const float* __restrict__ Sinv, float* __restrict__ O)
{
    extern __shared__ char sm[];
    const uint32_t sb = smem_u32(sm);

    const int tid  = threadIdx.x;
    const int wid  = tid >> 5;
    const int lane = tid & 31;
    const int g    = lane >> 2;
    const int tig  = lane & 3;
    const int mOff = (wid >> 2) * 64;   // 0,64   (d)
    const int nOff = (wid & 3) * 32;    // 0..96  (c)

    const int n  = blockIdx.z;
    const uint32_t* Vn = Vh + (size_t)n * DIM * (TT/2);
    const uint32_t* Wn = Wp + (size_t)n * CQ  * (TT/2);
    float*          Ob = O  + (size_t)n * DIM * CQ;
    const int d0 = blockIdx.y * 128;
    const int c0 = blockIdx.x * 128;

    // loaders: 2 threads per row, 8 words each (2 cp16) per stage
    const int lr  = tid >> 1;
    const int ls  = tid & 1;
    const uint32_t* vsrc = Vn + (size_t)(d0 + lr) * (TT/2) + ls * 8;
    const uint32_t* wsrc = Wn + (size_t)(c0 + lr) * (TT/2) + ls * 8;
    const uint32_t adst = sb + (uint32_t)(lr * 80 + ls * 32);
    const uint32_t bdst = sb + 10240u + (uint32_t)(lr * 80 + ls * 32);

    // ---- ldmatrix per-thread relative byte offsets (stage-invariant) ----
    // A (m16 x k16 tile i): lanes 0-15 -> rows 0-15 kgroup0, 16-31 -> kgroup1.
    const int aRow = lane & 15;
    const int aKg  = lane >> 4;
    uint32_t aRel[4];
    #pragma unroll
    for (int i = 0; i < 4; i++)
        aRel[i] = (uint32_t)((mOff + 16 * i + aRow) * 80 + aKg * 16);
    // B (two n8 x k16 tiles per x4): m0=(nj,kg0) m1=(nj,kg1) m2=(nj+8,kg0) m3=(nj+8,kg1)
    const int bRow = (lane & 7) + ((lane >> 4) << 3);
    const int bKg  = (lane >> 3) & 1;
    uint32_t bRel[2];
    #pragma unroll
    for (int jj = 0; jj < 2; jj++)
        bRel[jj] = 10240u + (uint32_t)((nOff + 16 * jj + bRow) * 80 + bKg * 16);

    float acc[4][4][4];
    #pragma unroll
    for (int i = 0; i < 4; i++)
        #pragma unroll
        for (int j = 0; j < 4; j++)
            #pragma unroll
            for (int r = 0; r < 4; r++) acc[i][j][r] = 0.f;

    #pragma unroll
    for (int s = 0; s < 3; s++) {
        #pragma unroll
        for (int q = 0; q < 2; q++) {
            cp16(adst + s * S2 + q * 16, vsrc + s * 16 + q * 4);
            cp16(bdst + s * S2 + q * 16, wsrc + s * 16 + q * 4);
        }
        asm volatile("cp.async.commit_group;" ::: "memory");
    }

    asm volatile("cp.async.wait_group 2;" ::: "memory");
    __syncthreads();

    uint32_t af[2][4][4], bf[2][4][2];
    {
        const uint32_t st = sb;
        #pragma unroll
        for (int i = 0; i < 4; i++) ldsm4(af[0][i], st + aRel[i]);
        #pragma unroll
        for (int jj = 0; jj < 2; jj++) {
            uint32_t t4[4];
            ldsm4(t4, st + bRel[jj]);
            bf[0][2*jj][0] = t4[0]; bf[0][2*jj][1] = t4[1];
            bf[0][2*jj+1][0] = t4[2]; bf[0][2*jj+1][1] = t4[3];
        }
    }

    for (int c = 0; c < 32; c++) {
        const uint32_t st = sb + (c & 3) * S2;

        // prefetch ks=1 frags (byte offset +32 = k16), run ks=0 MMAs
        #pragma unroll
        for (int i = 0; i < 4; i++) ldsm4(af[1][i], st + aRel[i] + 32);
        #pragma unroll
        for (int jj = 0; jj < 2; jj++) {
            uint32_t t4[4];
            ldsm4(t4, st + bRel[jj] + 32);
            bf[1][2*jj][0] = t4[0]; bf[1][2*jj][1] = t4[1];
            bf[1][2*jj+1][0] = t4[2]; bf[1][2*jj+1][1] = t4[3];
        }
        #pragma unroll
        for (int i = 0; i < 4; i++)
            #pragma unroll
            for (int j = 0; j < 4; j++)
                mma_f16(acc[i][j], af[0][i][0], af[0][i][1], af[0][i][2], af[0][i][3],
                        bf[0][j][0], bf[0][j][1]);

        {
            const int s = c + 3;
            if (s < 32) {
                #pragma unroll
                for (int q = 0; q < 2; q++) {
                    cp16(adst + (s & 3) * S2 + q * 16, vsrc + (size_t)s * 16 + q * 4);
                    cp16(bdst + (s & 3) * S2 + q * 16, wsrc + (size_t)s * 16 + q * 4);
                }
            }
            asm volatile("cp.async.commit_group;" ::: "memory");
        }
        asm volatile("cp.async.wait_group 2;" ::: "memory");
        __syncthreads();

        // prefetch next chunk ks=0 frags, run ks=1 MMAs
        if (c + 1 < 32) {
            const uint32_t sn = sb + ((c + 1) & 3) * S2;
            #pragma unroll
            for (int i = 0; i < 4; i++) ldsm4(af[0][i], sn + aRel[i]);
            #pragma unroll
            for (int jj = 0; jj < 2; jj++) {
                uint32_t t4[4];
                ldsm4(t4, sn + bRel[jj]);
                bf[0][2*jj][0] = t4[0]; bf[0][2*jj][1] = t4[1];
                bf[0][2*jj+1][0] = t4[2]; bf[0][2*jj+1][1] = t4[3];
            }
        }
        #pragma unroll
        for (int i = 0; i < 4; i++)
            #pragma unroll
            for (int j = 0; j < 4; j++)
                mma_f16(acc[i][j], af[1][i][0], af[1][i][1], af[1][i][2], af[1][i][3],
                        bf[1][j][0], bf[1][j][1]);
    }

    const float* Sn = Sinv + (size_t)n * CQ;
    #pragma unroll
    for (int i = 0; i < 4; i++) {
        const int row0 = d0 + mOff + 16 * i + g;
        #pragma unroll
        for (int j = 0; j < 4; j++) {
            const int colb = c0 + nOff + 8 * j + 2 * tig;
            const float si0 = Sn[colb];
            const float si1 = Sn[colb + 1];
            *(float2*)(Ob + (size_t)row0 * CQ + colb) =
                make_float2(acc[i][j][0] * si0, acc[i][j][1] * si1);
            *(float2*)(Ob + (size_t)(row0 + 8) * CQ + colb) =
                make_float2(acc[i][j][2] * si0, acc[i][j][3] * si1);
        }
    }
}

// ---------------------------------------------------------------------------
extern "C" void kernel_launch(void* const* d_in, const int* in_sizes, int n_in,
                              void* d_out, int out_size)
{
    const float* query  = (const float*)d_in[0];  // [64, 512, 512]
    const float* key    = (const float*)d_in[1];  // [64, 512, 1024]
    const float* value  = (const float*)d_in[2];  // [64, 512, 1024]
    const float* ratios = (const float*)d_in[3];  // [64]
    float* out = (float*)d_out;                   // [64, 512, 512]

    __half*   wh = nullptr;
    uint32_t *qh = nullptr, *kh = nullptr, *vh = nullptr;
    float    *sp = nullptr, *si = nullptr;
    cudaGetSymbolAddress((void**)&wh, g_wh);
    cudaGetSymbolAddress((void**)&qh, g_qh);
    cudaGetSymbolAddress((void**)&kh, g_kh);
    cudaGetSymbolAddress((void**)&vh, g_vh);
    cudaGetSymbolAddress((void**)&sp, g_Spart);
    cudaGetSymbolAddress((void**)&si, g_Sinv);

    cudaFuncSetAttribute(gemm_qk, cudaFuncAttributeMaxDynamicSharedMemorySize, SMEM1);
    cudaFuncSetAttribute(gemm_wv, cudaFuncAttributeMaxDynamicSharedMemorySize, SMEM2);

    // 0) conversions
    pairify<<<dim3(CQ / 512, DIM / 2, N_BATCH), 128>>>(query, qh, CQ, SCALE);
    pairify<<<dim3(TT / 512, DIM / 2, N_BATCH), 128>>>(key,   kh, TT, 1.0f);
    {
        const size_t n8 = (size_t)N_BATCH * DIM * TT / 8;
        vconv<<<(unsigned)(n8 / 256), 256>>>((const float4*)value, (uint4*)vh);
    }
    // 1) e = mask?exp((Q*SCALE)^T K):0  + partial sums
    {
        dim3 grid(TT / 128, CQ / 256, N_BATCH);  // (8, 2, 64)
        gemm_qk<<<grid, 256, SMEM1>>>(qh, kh, wh, sp, ratios);
    }
    // 2) Sinv = 1/rowsum
    sinv_kernel<<<(N_BATCH * CQ) / 256, 256>>>(sp, si);
    // 3) out = Sinv .* (V x e^T)
    {
        dim3 grid(CQ / 128, DIM / 128, N_BATCH);  // (4, 4, 64)
        gemm_wv<<<grid, 256, SMEM2>>>(vh, (const uint32_t*)wh, si, out);
    }
}